// round 1
// baseline (speedup 1.0000x reference)
#include <cuda_runtime.h>
#include <math.h>

// Problem constants
#define Bq  2
#define Sq  2048
#define Dm  1024
#define Hh  16
#define HDc 64
#define Mtot (Bq*Sq)   // 4096

// Device scratch (allocation rules: __device__ globals only)
__device__ float g_Q[Bq*Hh*Sq*HDc];   // (B,H,S,HD)
__device__ float g_K[Bq*Hh*Sq*HDc];
__device__ float g_V[Bq*Hh*Sq*HDc];
__device__ float g_A[Bq*Sq*Dm];       // attention output, (B,S,D)

// ---------------------------------------------------------------------------
// SGEMM: C[M=4096][N=1024] = A[M][1024] @ W[1024][N]
// BM=BN=128, BK=16, 256 threads, 8x8 register tile.
// split==1: write to head-split layout dst[((b*H+h)*S+s)*HD + hd]
// split==0: plain row-major dst[m*1024 + n]
// ---------------------------------------------------------------------------
__global__ __launch_bounds__(256) void sgemm_k(const float* __restrict__ A,
                                               const float* __restrict__ W,
                                               float* __restrict__ dst,
                                               int split)
{
    __shared__ float As[16][132];  // padded: conflict-free transposed stores
    __shared__ float Bs[16][128];

    const int tid = threadIdx.x;
    const int rowBase = blockIdx.y * 128;
    const int colBase = blockIdx.x * 128;

    // A-tile load mapping: 128 rows x 16 cols, float4 along k
    const int arow = tid >> 2;          // 0..63 (two passes for 128 rows)
    const int acol = (tid & 3) * 4;     // 0,4,8,12
    // B-tile load mapping: 16 rows x 128 cols, float4 along n
    const int brow = tid >> 5;          // 0..7 (two passes for 16 rows)
    const int bcol = (tid & 31) * 4;

    const int ty = tid >> 4;            // 0..15
    const int tx = tid & 15;            // 0..15

    float acc[8][8];
    #pragma unroll
    for (int i = 0; i < 8; i++)
        #pragma unroll
        for (int j = 0; j < 8; j++) acc[i][j] = 0.f;

    for (int k0 = 0; k0 < 1024; k0 += 16) {
        #pragma unroll
        for (int r = 0; r < 2; r++) {
            int m = arow + r * 64;
            float4 v = *(const float4*)&A[(size_t)(rowBase + m) * 1024 + k0 + acol];
            As[acol + 0][m] = v.x;
            As[acol + 1][m] = v.y;
            As[acol + 2][m] = v.z;
            As[acol + 3][m] = v.w;
        }
        #pragma unroll
        for (int r = 0; r < 2; r++) {
            int k = brow + r * 8;
            float4 v = *(const float4*)&W[(size_t)(k0 + k) * 1024 + colBase + bcol];
            *(float4*)&Bs[k][bcol] = v;
        }
        __syncthreads();

        #pragma unroll
        for (int k = 0; k < 16; k++) {
            float4 ra0 = *(const float4*)&As[k][ty * 8 + 0];
            float4 ra1 = *(const float4*)&As[k][ty * 8 + 4];
            float4 rb0 = *(const float4*)&Bs[k][tx * 8 + 0];
            float4 rb1 = *(const float4*)&Bs[k][tx * 8 + 4];
            float ra[8] = {ra0.x, ra0.y, ra0.z, ra0.w, ra1.x, ra1.y, ra1.z, ra1.w};
            float rb[8] = {rb0.x, rb0.y, rb0.z, rb0.w, rb1.x, rb1.y, rb1.z, rb1.w};
            #pragma unroll
            for (int i = 0; i < 8; i++)
                #pragma unroll
                for (int j = 0; j < 8; j++)
                    acc[i][j] += ra[i] * rb[j];
        }
        __syncthreads();
    }

    if (split == 0) {
        #pragma unroll
        for (int i = 0; i < 8; i++) {
            int m = rowBase + ty * 8 + i;
            #pragma unroll
            for (int j = 0; j < 8; j += 4) {
                float4 v = make_float4(acc[i][j], acc[i][j+1], acc[i][j+2], acc[i][j+3]);
                *(float4*)&dst[(size_t)m * 1024 + colBase + tx * 8 + j] = v;
            }
        }
    } else {
        #pragma unroll
        for (int i = 0; i < 8; i++) {
            int m = rowBase + ty * 8 + i;
            int b = m >> 11;            // m / 2048
            int s = m & 2047;
            #pragma unroll
            for (int j = 0; j < 8; j += 4) {
                int n = colBase + tx * 8 + j;
                int h  = n >> 6;
                int hd = n & 63;
                float4 v = make_float4(acc[i][j], acc[i][j+1], acc[i][j+2], acc[i][j+3]);
                *(float4*)&dst[(size_t)(((b * Hh + h) * Sq) + s) * HDc + hd] = v;
            }
        }
    }
}

// ---------------------------------------------------------------------------
// Causal flash attention (fp32). One block per (q-tile of 64, h, b).
// 256 threads: thread t -> row q = t>>2, k-slice cg = t&3 (k = cg + 4j).
// Online softmax; per-thread output slice of 16 head dims.
// ---------------------------------------------------------------------------
#define APITCH 68

__global__ __launch_bounds__(256) void attn_k(const float* __restrict__ Qg,
                                              const float* __restrict__ Kg,
                                              const float* __restrict__ Vg,
                                              float* __restrict__ Ag)
{
    extern __shared__ float sm[];
    float* Qs = sm;                    // 64 x APITCH
    float* Ks = sm + 64 * APITCH;
    float* Vs = sm + 2 * 64 * APITCH;
    float* Ps = sm + 3 * 64 * APITCH;

    const int tid = threadIdx.x;
    const int q0 = blockIdx.x * 64;
    const int h  = blockIdx.y;
    const int b  = blockIdx.z;

    const float* Qb = Qg + (size_t)((b * Hh + h) * Sq) * HDc;
    const float* Kb = Kg + (size_t)((b * Hh + h) * Sq) * HDc;
    const float* Vb = Vg + (size_t)((b * Hh + h) * Sq) * HDc;

    const int q  = tid >> 2;   // 0..63
    const int cg = tid & 3;    // 0..3

    // load + pre-scale Q tile (1/sqrt(64) = 0.125)
    for (int i = tid; i < 64 * 16; i += 256) {
        int r = i >> 4, c = (i & 15) * 4;
        float4 v = *(const float4*)&Qb[(size_t)(q0 + r) * HDc + c];
        Qs[r * APITCH + c + 0] = v.x * 0.125f;
        Qs[r * APITCH + c + 1] = v.y * 0.125f;
        Qs[r * APITCH + c + 2] = v.z * 0.125f;
        Qs[r * APITCH + c + 3] = v.w * 0.125f;
    }

    float m = -INFINITY, l = 0.f;
    float o[16];
    #pragma unroll
    for (int i = 0; i < 16; i++) o[i] = 0.f;

    for (int k0 = 0; k0 <= q0; k0 += 64) {
        __syncthreads();   // previous-iter readers of Ks/Vs done (also covers Qs fill)
        for (int i = tid; i < 64 * 16; i += 256) {
            int r = i >> 4, c = (i & 15) * 4;
            float4 kv = *(const float4*)&Kb[(size_t)(k0 + r) * HDc + c];
            Ks[r * APITCH + c + 0] = kv.x;
            Ks[r * APITCH + c + 1] = kv.y;
            Ks[r * APITCH + c + 2] = kv.z;
            Ks[r * APITCH + c + 3] = kv.w;
            float4 vv = *(const float4*)&Vb[(size_t)(k0 + r) * HDc + c];
            Vs[r * APITCH + c + 0] = vv.x;
            Vs[r * APITCH + c + 1] = vv.y;
            Vs[r * APITCH + c + 2] = vv.z;
            Vs[r * APITCH + c + 3] = vv.w;
        }
        __syncthreads();

        // scores: s[j] = Qrow . K(cg+4j)
        float s[16];
        #pragma unroll
        for (int j = 0; j < 16; j++) s[j] = 0.f;
        #pragma unroll
        for (int d4 = 0; d4 < 64; d4 += 4) {
            float4 qv = *(const float4*)&Qs[q * APITCH + d4];
            #pragma unroll
            for (int j = 0; j < 16; j++) {
                float4 kv = *(const float4*)&Ks[(cg + 4 * j) * APITCH + d4];
                s[j] += qv.x * kv.x + qv.y * kv.y + qv.z * kv.z + qv.w * kv.w;
            }
        }

        if (k0 == q0) {   // diagonal tile: causal mask
            #pragma unroll
            for (int j = 0; j < 16; j++)
                if (cg + 4 * j > q) s[j] = -INFINITY;
        }

        // row max across the 4 threads of this row (aligned lane group)
        float tm = s[0];
        #pragma unroll
        for (int j = 1; j < 16; j++) tm = fmaxf(tm, s[j]);
        tm = fmaxf(tm, __shfl_xor_sync(0xffffffffu, tm, 1));
        tm = fmaxf(tm, __shfl_xor_sync(0xffffffffu, tm, 2));
        float mnew = fmaxf(m, tm);
        float corr = __expf(m - mnew);   // 0 on first tile (m = -inf)

        float lsum = 0.f;
        #pragma unroll
        for (int j = 0; j < 16; j++) {
            float p = __expf(s[j] - mnew);
            Ps[q * APITCH + cg + 4 * j] = p;
            lsum += p;
        }
        lsum += __shfl_xor_sync(0xffffffffu, lsum, 1);
        lsum += __shfl_xor_sync(0xffffffffu, lsum, 2);
        l = l * corr + lsum;
        m = mnew;
        #pragma unroll
        for (int dd = 0; dd < 16; dd++) o[dd] *= corr;

        __syncwarp();  // P row is produced/consumed entirely within one warp

        // O += P @ V  (this thread: row q, head dims cg*16 .. cg*16+15)
        #pragma unroll
        for (int k4 = 0; k4 < 64; k4 += 4) {
            float4 p4 = *(const float4*)&Ps[q * APITCH + k4];
            float pk[4] = {p4.x, p4.y, p4.z, p4.w};
            #pragma unroll
            for (int kk = 0; kk < 4; kk++) {
                const float* vrow = &Vs[(k4 + kk) * APITCH + cg * 16];
                float4 v0 = *(const float4*)&vrow[0];
                float4 v1 = *(const float4*)&vrow[4];
                float4 v2 = *(const float4*)&vrow[8];
                float4 v3 = *(const float4*)&vrow[12];
                float pv = pk[kk];
                o[0]  += pv * v0.x; o[1]  += pv * v0.y; o[2]  += pv * v0.z; o[3]  += pv * v0.w;
                o[4]  += pv * v1.x; o[5]  += pv * v1.y; o[6]  += pv * v1.z; o[7]  += pv * v1.w;
                o[8]  += pv * v2.x; o[9]  += pv * v2.y; o[10] += pv * v2.z; o[11] += pv * v2.w;
                o[12] += pv * v3.x; o[13] += pv * v3.y; o[14] += pv * v3.z; o[15] += pv * v3.w;
            }
        }
    }

    // write out in (B, S, D) layout: Ag[(b*S + q0+q)*D + h*64 + cg*16 + dd]
    float inv = 1.f / l;
    float* dstp = Ag + (size_t)(b * Sq + q0 + q) * Dm + h * HDc + cg * 16;
    #pragma unroll
    for (int dd = 0; dd < 16; dd += 4) {
        float4 v = make_float4(o[dd] * inv, o[dd+1] * inv, o[dd+2] * inv, o[dd+3] * inv);
        *(float4*)&dstp[dd] = v;
    }
}

// ---------------------------------------------------------------------------
extern "C" void kernel_launch(void* const* d_in, const int* in_sizes, int n_in,
                              void* d_out, int out_size)
{
    (void)in_sizes; (void)n_in; (void)out_size;
    const float* x  = (const float*)d_in[0];
    const float* WQ = (const float*)d_in[1];
    const float* WK = (const float*)d_in[2];
    const float* WV = (const float*)d_in[3];
    const float* WO = (const float*)d_in[4];
    // d_in[5] = mask: known causal, handled analytically.
    float* out = (float*)d_out;

    float *qp, *kp, *vp, *ap;
    cudaGetSymbolAddress((void**)&qp, g_Q);
    cudaGetSymbolAddress((void**)&kp, g_K);
    cudaGetSymbolAddress((void**)&vp, g_V);
    cudaGetSymbolAddress((void**)&ap, g_A);

    dim3 gg(Dm / 128, Mtot / 128);
    sgemm_k<<<gg, 256>>>(x, WQ, qp, 1);
    sgemm_k<<<gg, 256>>>(x, WK, kp, 1);
    sgemm_k<<<gg, 256>>>(x, WV, vp, 1);

    int smem = 4 * 64 * APITCH * (int)sizeof(float);  // 69632 B
    cudaFuncSetAttribute(attn_k, cudaFuncAttributeMaxDynamicSharedMemorySize, smem);
    attn_k<<<dim3(Sq / 64, Hh, Bq), 256, smem>>>(qp, kp, vp, ap);

    sgemm_k<<<gg, 256>>>(ap, WO, out, 0);
}

// round 3
// speedup vs baseline: 1.1944x; 1.1944x over previous
#include <cuda_runtime.h>
#include <cuda_bf16.h>
#include <math.h>
#include <stdint.h>

// Problem constants
#define Bq  2
#define Sq  2048
#define Dm  1024
#define Hh  16
#define HDc 64
#define Mtot (Bq*Sq)   // 4096

// ---------------- device scratch (no allocs allowed) ----------------
__device__ float g_Q[Bq*Hh*Sq*HDc];   // (B,H,S,HD)
__device__ float g_K[Bq*Hh*Sq*HDc];
__device__ float g_V[Bq*Hh*Sq*HDc];
__device__ float g_A[Bq*Sq*Dm];       // attention output, (B,S,D)

__device__ __nv_bfloat16 g_Xh[Mtot*Dm];    // x split hi/lo, [M][K]
__device__ __nv_bfloat16 g_Xl[Mtot*Dm];
__device__ __nv_bfloat16 g_Wh[4][Dm*Dm];   // W^T split hi/lo, [N][K]
__device__ __nv_bfloat16 g_Wl[4][Dm*Dm];
__device__ __nv_bfloat16 g_AH[Mtot*Dm];    // attention-out split hi/lo
__device__ __nv_bfloat16 g_AL[Mtot*Dm];

// ---------------- helpers ----------------
__device__ __forceinline__ uint32_t smem_u32(const void* p) {
    uint32_t a;
    asm("{ .reg .u64 t; cvta.to.shared.u64 t, %1; cvt.u32.u64 %0, t; }" : "=r"(a) : "l"(p));
    return a;
}
__device__ __forceinline__ void cp16(uint32_t saddr, const void* gptr) {
    asm volatile("cp.async.cg.shared.global [%0], [%1], 16;" :: "r"(saddr), "l"(gptr) : "memory");
}
__device__ __forceinline__ void cp_commit() {
    asm volatile("cp.async.commit_group;" ::: "memory");
}
__device__ __forceinline__ void cp_wait0() {
    asm volatile("cp.async.wait_group 0;" ::: "memory");
}
__device__ __forceinline__ void ldsm_x4(uint32_t* r, uint32_t a) {
    asm volatile("ldmatrix.sync.aligned.m8n8.x4.shared.b16 {%0,%1,%2,%3}, [%4];"
                 : "=r"(r[0]), "=r"(r[1]), "=r"(r[2]), "=r"(r[3]) : "r"(a));
}
__device__ __forceinline__ void ldsm_x2(uint32_t* r, uint32_t a) {
    asm volatile("ldmatrix.sync.aligned.m8n8.x2.shared.b16 {%0,%1}, [%2];"
                 : "=r"(r[0]), "=r"(r[1]) : "r"(a));
}
__device__ __forceinline__ void mma16816(float* c, const uint32_t* a, const uint32_t* b) {
    asm volatile(
        "mma.sync.aligned.m16n8k16.row.col.f32.bf16.bf16.f32 "
        "{%0,%1,%2,%3}, {%4,%5,%6,%7}, {%8,%9}, {%0,%1,%2,%3};"
        : "+f"(c[0]), "+f"(c[1]), "+f"(c[2]), "+f"(c[3])
        : "r"(a[0]), "r"(a[1]), "r"(a[2]), "r"(a[3]), "r"(b[0]), "r"(b[1]));
}

// ---------------------------------------------------------------------------
// split-bf16 conversion, elementwise
// ---------------------------------------------------------------------------
__global__ __launch_bounds__(256) void convx_k(const float* __restrict__ X,
                                               __nv_bfloat16* __restrict__ H,
                                               __nv_bfloat16* __restrict__ L)
{
    int i = blockIdx.x * blockDim.x + threadIdx.x;   // one float4
    float4 v = ((const float4*)X)[i];
    __nv_bfloat16 h0 = __float2bfloat16(v.x), h1 = __float2bfloat16(v.y);
    __nv_bfloat16 h2 = __float2bfloat16(v.z), h3 = __float2bfloat16(v.w);
    __nv_bfloat16 l0 = __float2bfloat16(v.x - __bfloat162float(h0));
    __nv_bfloat16 l1 = __float2bfloat16(v.y - __bfloat162float(h1));
    __nv_bfloat16 l2 = __float2bfloat16(v.z - __bfloat162float(h2));
    __nv_bfloat16 l3 = __float2bfloat16(v.w - __bfloat162float(h3));
    __nv_bfloat162* H2 = (__nv_bfloat162*)H;
    __nv_bfloat162* L2 = (__nv_bfloat162*)L;
    __nv_bfloat162 a; a.x = h0; a.y = h1; H2[2*i] = a;
    __nv_bfloat162 b; b.x = h2; b.y = h3; H2[2*i+1] = b;
    __nv_bfloat162 c; c.x = l0; c.y = l1; L2[2*i] = c;
    __nv_bfloat162 d; d.x = l2; d.y = l3; L2[2*i+1] = d;
}

// transpose + split: W[K][N] fp32 -> Wt_hi/lo[N][K] bf16
__global__ __launch_bounds__(256) void convw_k(const float* __restrict__ W,
                                               __nv_bfloat16* __restrict__ Th,
                                               __nv_bfloat16* __restrict__ Tl)
{
    __shared__ float t[32][33];
    int n0 = blockIdx.x * 32, k0 = blockIdx.y * 32;
    int tx = threadIdx.x, ty = threadIdx.y;   // 32 x 8
    #pragma unroll
    for (int j = ty; j < 32; j += 8)
        t[j][tx] = W[(size_t)(k0 + j) * Dm + n0 + tx];
    __syncthreads();
    #pragma unroll
    for (int j = ty; j < 32; j += 8) {
        float v = t[tx][j];   // = W[k0+tx][n0+j]
        __nv_bfloat16 h = __float2bfloat16(v);
        float l = v - __bfloat162float(h);
        size_t o = (size_t)(n0 + j) * Dm + k0 + tx;
        Th[o] = h;
        Tl[o] = __float2bfloat16(l);
    }
}

// ---------------------------------------------------------------------------
// HMMA split-bf16 GEMM: C[4096][1024] = A @ B^T  (B stored [N][K])
// C = Ah@Bh + Ah@Bl + Al@Bh, fp32 accum.
// CTA 128x128, BK=32, 256 thr (8 warps, 2x4), warp tile 64x32, mma.m16n8k16.
// Double-buffered cp.async. Pitch 40 bf16 (80B) rows: conflict-free ldmatrix.
// ---------------------------------------------------------------------------
#define GP 40            // smem row pitch in bf16 elems
#define MATB (128*GP*2)  // bytes per matrix tile: 10240
#define STAGEB (4*MATB)  // 40960

__global__ __launch_bounds__(256) void gemm_mma(
    const __nv_bfloat16* __restrict__ Agh, const __nv_bfloat16* __restrict__ Agl,
    const __nv_bfloat16* __restrict__ Bgh, const __nv_bfloat16* __restrict__ Bgl,
    float* __restrict__ dst, int split)
{
    extern __shared__ char smc[];
    const uint32_t sb = smem_u32(smc);
    const int tid = threadIdx.x, lane = tid & 31, w = tid >> 5;
    const int wr = w >> 2, wc = w & 3;           // 2 x 4 warp grid
    const int rowBase = blockIdx.y * 128, colBase = blockIdx.x * 128;

    const __nv_bfloat16* gAh = Agh + (size_t)rowBase * Dm;
    const __nv_bfloat16* gAl = Agl + (size_t)rowBase * Dm;
    const __nv_bfloat16* gBh = Bgh + (size_t)colBase * Dm;
    const __nv_bfloat16* gBl = Bgl + (size_t)colBase * Dm;

    float acc[4][4][4];
    #pragma unroll
    for (int t = 0; t < 4; t++)
        #pragma unroll
        for (int j = 0; j < 4; j++)
            #pragma unroll
            for (int e = 0; e < 4; e++) acc[t][j][e] = 0.f;

    // per-thread load mapping (chunk = 16B): chunk -> row, col16
    const int r0 = tid >> 2, c0 = tid & 3;          // chunk tid
    const int r1 = (tid + 256) >> 2, c1 = (tid + 256) & 3;

    // issue loads for k-tile kt into buffer buf
    auto issue = [&](int kt, int buf) {
        const int kc = kt * 32;
        const uint32_t base = sb + buf * STAGEB;
        {
            uint32_t so = (uint32_t)(r0 * (GP*2) + c0 * 16);
            size_t  go = (size_t)r0 * Dm + kc + c0 * 8;
            cp16(base + 0*MATB + so, gAh + go);
            cp16(base + 1*MATB + so, gAl + go);
            cp16(base + 2*MATB + so, gBh + go);
            cp16(base + 3*MATB + so, gBl + go);
        }
        {
            uint32_t so = (uint32_t)(r1 * (GP*2) + c1 * 16);
            size_t  go = (size_t)r1 * Dm + kc + c1 * 8;
            cp16(base + 0*MATB + so, gAh + go);
            cp16(base + 1*MATB + so, gAl + go);
            cp16(base + 2*MATB + so, gBh + go);
            cp16(base + 3*MATB + so, gBl + go);
        }
        cp_commit();
    };

    // ldmatrix lane addressing (element offsets within a tile)
    const int aRow = wr * 64 + (lane & 15);
    const int aKh  = (lane >> 4) * 8;
    const int bRowL = wc * 32 + (lane & 7);
    const int bKh   = ((lane >> 3) & 1) * 8;

    issue(0, 0);

    for (int kt = 0; kt < 32; kt++) {
        cp_wait0();
        __syncthreads();
        if (kt + 1 < 32) issue(kt + 1, (kt + 1) & 1);

        const uint32_t base = sb + (kt & 1) * STAGEB;
        #pragma unroll
        for (int kk = 0; kk < 2; kk++) {
            uint32_t bh[4][2], bl[4][2];
            #pragma unroll
            for (int j = 0; j < 4; j++) {
                uint32_t ba = base + 2*MATB +
                    (uint32_t)(((bRowL + j * 8) * GP + kk * 16 + bKh) * 2);
                ldsm_x2(bh[j], ba);
                ldsm_x2(bl[j], ba + MATB);
            }
            #pragma unroll
            for (int t = 0; t < 4; t++) {
                uint32_t aa = base +
                    (uint32_t)(((aRow + t * 16) * GP + kk * 16 + aKh) * 2);
                uint32_t ah[4], al[4];
                ldsm_x4(ah, aa);
                ldsm_x4(al, aa + MATB);
                #pragma unroll
                for (int j = 0; j < 4; j++) {
                    mma16816(acc[t][j], ah, bh[j]);
                    mma16816(acc[t][j], ah, bl[j]);
                    mma16816(acc[t][j], al, bh[j]);
                }
            }
        }
        __syncthreads();
    }

    // epilogue
    const int er = lane >> 2, ec = (lane & 3) * 2;
    #pragma unroll
    for (int t = 0; t < 4; t++) {
        #pragma unroll
        for (int j = 0; j < 4; j++) {
            int m0 = rowBase + wr * 64 + t * 16 + er;
            int n  = colBase + wc * 32 + j * 8 + ec;
            float2 lo = make_float2(acc[t][j][0], acc[t][j][1]);
            float2 hi = make_float2(acc[t][j][2], acc[t][j][3]);
            if (split) {
                int h = n >> 6, hd = n & 63;
                int b0 = m0 >> 11, s0 = m0 & 2047;
                int b1 = (m0 + 8) >> 11, s1 = (m0 + 8) & 2047;
                *(float2*)&dst[((size_t)((b0 * Hh + h) * Sq + s0)) * HDc + hd] = lo;
                *(float2*)&dst[((size_t)((b1 * Hh + h) * Sq + s1)) * HDc + hd] = hi;
            } else {
                *(float2*)&dst[(size_t)m0 * Dm + n] = lo;
                *(float2*)&dst[(size_t)(m0 + 8) * Dm + n] = hi;
            }
        }
    }
}

// ---------------------------------------------------------------------------
// Causal flash attention (fp32) — unchanged (known good).
// ---------------------------------------------------------------------------
#define APITCH 68

__global__ __launch_bounds__(256) void attn_k(const float* __restrict__ Qg,
                                              const float* __restrict__ Kg,
                                              const float* __restrict__ Vg,
                                              float* __restrict__ Ag)
{
    extern __shared__ float smf[];
    float* Qs = smf;
    float* Ks = smf + 64 * APITCH;
    float* Vs = smf + 2 * 64 * APITCH;
    float* Ps = smf + 3 * 64 * APITCH;

    const int tid = threadIdx.x;
    const int q0 = blockIdx.x * 64;
    const int h  = blockIdx.y;
    const int b  = blockIdx.z;

    const float* Qb = Qg + (size_t)((b * Hh + h) * Sq) * HDc;
    const float* Kb = Kg + (size_t)((b * Hh + h) * Sq) * HDc;
    const float* Vb = Vg + (size_t)((b * Hh + h) * Sq) * HDc;

    const int q  = tid >> 2;
    const int cg = tid & 3;

    for (int i = tid; i < 64 * 16; i += 256) {
        int r = i >> 4, c = (i & 15) * 4;
        float4 v = *(const float4*)&Qb[(size_t)(q0 + r) * HDc + c];
        Qs[r * APITCH + c + 0] = v.x * 0.125f;
        Qs[r * APITCH + c + 1] = v.y * 0.125f;
        Qs[r * APITCH + c + 2] = v.z * 0.125f;
        Qs[r * APITCH + c + 3] = v.w * 0.125f;
    }

    float m = -INFINITY, l = 0.f;
    float o[16];
    #pragma unroll
    for (int i = 0; i < 16; i++) o[i] = 0.f;

    for (int k0 = 0; k0 <= q0; k0 += 64) {
        __syncthreads();
        for (int i = tid; i < 64 * 16; i += 256) {
            int r = i >> 4, c = (i & 15) * 4;
            float4 kv = *(const float4*)&Kb[(size_t)(k0 + r) * HDc + c];
            Ks[r * APITCH + c + 0] = kv.x;
            Ks[r * APITCH + c + 1] = kv.y;
            Ks[r * APITCH + c + 2] = kv.z;
            Ks[r * APITCH + c + 3] = kv.w;
            float4 vv = *(const float4*)&Vb[(size_t)(k0 + r) * HDc + c];
            Vs[r * APITCH + c + 0] = vv.x;
            Vs[r * APITCH + c + 1] = vv.y;
            Vs[r * APITCH + c + 2] = vv.z;
            Vs[r * APITCH + c + 3] = vv.w;
        }
        __syncthreads();

        float s[16];
        #pragma unroll
        for (int j = 0; j < 16; j++) s[j] = 0.f;
        #pragma unroll
        for (int d4 = 0; d4 < 64; d4 += 4) {
            float4 qv = *(const float4*)&Qs[q * APITCH + d4];
            #pragma unroll
            for (int j = 0; j < 16; j++) {
                float4 kv = *(const float4*)&Ks[(cg + 4 * j) * APITCH + d4];
                s[j] += qv.x * kv.x + qv.y * kv.y + qv.z * kv.z + qv.w * kv.w;
            }
        }

        if (k0 == q0) {
            #pragma unroll
            for (int j = 0; j < 16; j++)
                if (cg + 4 * j > q) s[j] = -INFINITY;
        }

        float tm = s[0];
        #pragma unroll
        for (int j = 1; j < 16; j++) tm = fmaxf(tm, s[j]);
        tm = fmaxf(tm, __shfl_xor_sync(0xffffffffu, tm, 1));
        tm = fmaxf(tm, __shfl_xor_sync(0xffffffffu, tm, 2));
        float mnew = fmaxf(m, tm);
        float corr = __expf(m - mnew);

        float lsum = 0.f;
        #pragma unroll
        for (int j = 0; j < 16; j++) {
            float p = __expf(s[j] - mnew);
            Ps[q * APITCH + cg + 4 * j] = p;
            lsum += p;
        }
        lsum += __shfl_xor_sync(0xffffffffu, lsum, 1);
        lsum += __shfl_xor_sync(0xffffffffu, lsum, 2);
        l = l * corr + lsum;
        m = mnew;
        #pragma unroll
        for (int dd = 0; dd < 16; dd++) o[dd] *= corr;

        __syncwarp();

        #pragma unroll
        for (int k4 = 0; k4 < 64; k4 += 4) {
            float4 p4 = *(const float4*)&Ps[q * APITCH + k4];
            float pk[4] = {p4.x, p4.y, p4.z, p4.w};
            #pragma unroll
            for (int kk = 0; kk < 4; kk++) {
                const float* vrow = &Vs[(k4 + kk) * APITCH + cg * 16];
                float4 v0 = *(const float4*)&vrow[0];
                float4 v1 = *(const float4*)&vrow[4];
                float4 v2 = *(const float4*)&vrow[8];
                float4 v3 = *(const float4*)&vrow[12];
                float pv = pk[kk];
                o[0]  += pv * v0.x; o[1]  += pv * v0.y; o[2]  += pv * v0.z; o[3]  += pv * v0.w;
                o[4]  += pv * v1.x; o[5]  += pv * v1.y; o[6]  += pv * v1.z; o[7]  += pv * v1.w;
                o[8]  += pv * v2.x; o[9]  += pv * v2.y; o[10] += pv * v2.z; o[11] += pv * v2.w;
                o[12] += pv * v3.x; o[13] += pv * v3.y; o[14] += pv * v3.z; o[15] += pv * v3.w;
            }
        }
    }

    float inv = 1.f / l;
    float* dstp = Ag + (size_t)(b * Sq + q0 + q) * Dm + h * HDc + cg * 16;
    #pragma unroll
    for (int dd = 0; dd < 16; dd += 4) {
        float4 v = make_float4(o[dd] * inv, o[dd+1] * inv, o[dd+2] * inv, o[dd+3] * inv);
        *(float4*)&dstp[dd] = v;
    }
}

// ---------------------------------------------------------------------------
extern "C" void kernel_launch(void* const* d_in, const int* in_sizes, int n_in,
                              void* d_out, int out_size)
{
    (void)in_sizes; (void)n_in; (void)out_size;
    const float* x  = (const float*)d_in[0];
    const float* WQ = (const float*)d_in[1];
    const float* WK = (const float*)d_in[2];
    const float* WV = (const float*)d_in[3];
    const float* WO = (const float*)d_in[4];
    float* out = (float*)d_out;

    float *qp, *kp, *vp, *ap;
    __nv_bfloat16 *xh, *xl, *wh, *wl, *ah, *al;
    cudaGetSymbolAddress((void**)&qp, g_Q);
    cudaGetSymbolAddress((void**)&kp, g_K);
    cudaGetSymbolAddress((void**)&vp, g_V);
    cudaGetSymbolAddress((void**)&ap, g_A);
    cudaGetSymbolAddress((void**)&xh, g_Xh);
    cudaGetSymbolAddress((void**)&xl, g_Xl);
    cudaGetSymbolAddress((void**)&wh, g_Wh);
    cudaGetSymbolAddress((void**)&wl, g_Wl);
    cudaGetSymbolAddress((void**)&ah, g_AH);
    cudaGetSymbolAddress((void**)&al, g_AL);

    static int attrs_set = 0;
    int gsmem = 2 * STAGEB;                   // 81920
    int asmem = 4 * 64 * APITCH * (int)sizeof(float);
    if (!attrs_set) {
        cudaFuncSetAttribute(gemm_mma, cudaFuncAttributeMaxDynamicSharedMemorySize, gsmem);
        cudaFuncSetAttribute(attn_k, cudaFuncAttributeMaxDynamicSharedMemorySize, asmem);
        attrs_set = 1;
    }

    // split conversions
    convx_k<<<Mtot * Dm / 4 / 256, 256>>>(x, xh, xl);
    const float* Ws[4] = {WQ, WK, WV, WO};
    for (int i = 0; i < 4; i++)
        convw_k<<<dim3(32, 32), dim3(32, 8)>>>(Ws[i], wh + (size_t)i * Dm * Dm,
                                               wl + (size_t)i * Dm * Dm);

    // projections (HMMA), head-split epilogue
    dim3 gg(Dm / 128, Mtot / 128);
    gemm_mma<<<gg, 256, gsmem>>>(xh, xl, wh + 0 * (size_t)Dm * Dm, wl + 0 * (size_t)Dm * Dm, qp, 1);
    gemm_mma<<<gg, 256, gsmem>>>(xh, xl, wh + 1 * (size_t)Dm * Dm, wl + 1 * (size_t)Dm * Dm, kp, 1);
    gemm_mma<<<gg, 256, gsmem>>>(xh, xl, wh + 2 * (size_t)Dm * Dm, wl + 2 * (size_t)Dm * Dm, vp, 1);

    // attention (fp32)
    attn_k<<<dim3(Sq / 64, Hh, Bq), 256, asmem>>>(qp, kp, vp, ap);

    // output projection
    convx_k<<<Mtot * Dm / 4 / 256, 256>>>(ap, ah, al);
    gemm_mma<<<gg, 256, gsmem>>>(ah, al, wh + 3 * (size_t)Dm * Dm, wl + 3 * (size_t)Dm * Dm, out, 0);
}

// round 4
// speedup vs baseline: 4.4151x; 3.6967x over previous
#include <cuda_runtime.h>
#include <cuda_bf16.h>
#include <math.h>
#include <stdint.h>

// Problem constants
#define Bq  2
#define Sq  2048
#define Dm  1024
#define Hh  16
#define HDc 64
#define Mtot (Bq*Sq)   // 4096

// ---------------- device scratch (no allocs allowed) ----------------
__device__ float g_Q[Bq*Hh*Sq*HDc];   // (B,H,S,HD)
__device__ float g_K[Bq*Hh*Sq*HDc];
__device__ float g_V[Bq*Hh*Sq*HDc];
__device__ float g_A[Bq*Sq*Dm];       // attention output, (B,S,D)

__device__ __nv_bfloat16 g_Xh[Mtot*Dm];    // x split hi/lo, [M][K]
__device__ __nv_bfloat16 g_Xl[Mtot*Dm];
__device__ __nv_bfloat16 g_Wh[4][Dm*Dm];   // W^T split hi/lo, [N][K]
__device__ __nv_bfloat16 g_Wl[4][Dm*Dm];
__device__ __nv_bfloat16 g_AH[Mtot*Dm];
__device__ __nv_bfloat16 g_AL[Mtot*Dm];

// ---------------- helpers ----------------
__device__ __forceinline__ uint32_t smem_u32(const void* p) {
    uint32_t a;
    asm("{ .reg .u64 t; cvta.to.shared.u64 t, %1; cvt.u32.u64 %0, t; }" : "=r"(a) : "l"(p));
    return a;
}
__device__ __forceinline__ void cp16(uint32_t saddr, const void* gptr) {
    asm volatile("cp.async.cg.shared.global [%0], [%1], 16;" :: "r"(saddr), "l"(gptr) : "memory");
}
__device__ __forceinline__ void cp_commit() {
    asm volatile("cp.async.commit_group;" ::: "memory");
}
__device__ __forceinline__ void cp_wait0() {
    asm volatile("cp.async.wait_group 0;" ::: "memory");
}
__device__ __forceinline__ void ldsm_x4(uint32_t* r, uint32_t a) {
    asm volatile("ldmatrix.sync.aligned.m8n8.x4.shared.b16 {%0,%1,%2,%3}, [%4];"
                 : "=r"(r[0]), "=r"(r[1]), "=r"(r[2]), "=r"(r[3]) : "r"(a));
}
__device__ __forceinline__ void ldsm_x2(uint32_t* r, uint32_t a) {
    asm volatile("ldmatrix.sync.aligned.m8n8.x2.shared.b16 {%0,%1}, [%2];"
                 : "=r"(r[0]), "=r"(r[1]) : "r"(a));
}
__device__ __forceinline__ void ldsm_x2t(uint32_t* r, uint32_t a) {
    asm volatile("ldmatrix.sync.aligned.m8n8.x2.trans.shared.b16 {%0,%1}, [%2];"
                 : "=r"(r[0]), "=r"(r[1]) : "r"(a));
}
__device__ __forceinline__ void mma16816(float* c, const uint32_t* a, const uint32_t* b) {
    asm volatile(
        "mma.sync.aligned.m16n8k16.row.col.f32.bf16.bf16.f32 "
        "{%0,%1,%2,%3}, {%4,%5,%6,%7}, {%8,%9}, {%0,%1,%2,%3};"
        : "+f"(c[0]), "+f"(c[1]), "+f"(c[2]), "+f"(c[3])
        : "r"(a[0]), "r"(a[1]), "r"(a[2]), "r"(a[3]), "r"(b[0]), "r"(b[1]));
}
__device__ __forceinline__ uint32_t pack_split(float a, float b, uint32_t& lo) {
    __nv_bfloat16 ha = __float2bfloat16(a), hb = __float2bfloat16(b);
    __nv_bfloat16 la = __float2bfloat16(a - __bfloat162float(ha));
    __nv_bfloat16 lb = __float2bfloat16(b - __bfloat162float(hb));
    uint16_t uha = *(uint16_t*)&ha, uhb = *(uint16_t*)&hb;
    uint16_t ula = *(uint16_t*)&la, ulb = *(uint16_t*)&lb;
    lo = (uint32_t)ula | ((uint32_t)ulb << 16);
    return (uint32_t)uha | ((uint32_t)uhb << 16);
}

// ---------------------------------------------------------------------------
// split-bf16 conversion kernels (unchanged)
// ---------------------------------------------------------------------------
__global__ __launch_bounds__(256) void convx_k(const float* __restrict__ X,
                                               __nv_bfloat16* __restrict__ H,
                                               __nv_bfloat16* __restrict__ L)
{
    int i = blockIdx.x * blockDim.x + threadIdx.x;
    float4 v = ((const float4*)X)[i];
    __nv_bfloat16 h0 = __float2bfloat16(v.x), h1 = __float2bfloat16(v.y);
    __nv_bfloat16 h2 = __float2bfloat16(v.z), h3 = __float2bfloat16(v.w);
    __nv_bfloat16 l0 = __float2bfloat16(v.x - __bfloat162float(h0));
    __nv_bfloat16 l1 = __float2bfloat16(v.y - __bfloat162float(h1));
    __nv_bfloat16 l2 = __float2bfloat16(v.z - __bfloat162float(h2));
    __nv_bfloat16 l3 = __float2bfloat16(v.w - __bfloat162float(h3));
    __nv_bfloat162* H2 = (__nv_bfloat162*)H;
    __nv_bfloat162* L2 = (__nv_bfloat162*)L;
    __nv_bfloat162 a; a.x = h0; a.y = h1; H2[2*i] = a;
    __nv_bfloat162 b; b.x = h2; b.y = h3; H2[2*i+1] = b;
    __nv_bfloat162 c; c.x = l0; c.y = l1; L2[2*i] = c;
    __nv_bfloat162 d; d.x = l2; d.y = l3; L2[2*i+1] = d;
}

__global__ __launch_bounds__(256) void convw_k(const float* __restrict__ W,
                                               __nv_bfloat16* __restrict__ Th,
                                               __nv_bfloat16* __restrict__ Tl)
{
    __shared__ float t[32][33];
    int n0 = blockIdx.x * 32, k0 = blockIdx.y * 32;
    int tx = threadIdx.x, ty = threadIdx.y;
    #pragma unroll
    for (int j = ty; j < 32; j += 8)
        t[j][tx] = W[(size_t)(k0 + j) * Dm + n0 + tx];
    __syncthreads();
    #pragma unroll
    for (int j = ty; j < 32; j += 8) {
        float v = t[tx][j];
        __nv_bfloat16 h = __float2bfloat16(v);
        float l = v - __bfloat162float(h);
        size_t o = (size_t)(n0 + j) * Dm + k0 + tx;
        Th[o] = h;
        Tl[o] = __float2bfloat16(l);
    }
}

// ---------------------------------------------------------------------------
// HMMA split-bf16 GEMM (unchanged from R3, known good)
// ---------------------------------------------------------------------------
#define GP 40
#define MATB (128*GP*2)
#define STAGEB (4*MATB)

__global__ __launch_bounds__(256) void gemm_mma(
    const __nv_bfloat16* __restrict__ Agh, const __nv_bfloat16* __restrict__ Agl,
    const __nv_bfloat16* __restrict__ Bgh, const __nv_bfloat16* __restrict__ Bgl,
    float* __restrict__ dst, int split)
{
    extern __shared__ char smc[];
    const uint32_t sb = smem_u32(smc);
    const int tid = threadIdx.x, lane = tid & 31, w = tid >> 5;
    const int wr = w >> 2, wc = w & 3;
    const int rowBase = blockIdx.y * 128, colBase = blockIdx.x * 128;

    const __nv_bfloat16* gAh = Agh + (size_t)rowBase * Dm;
    const __nv_bfloat16* gAl = Agl + (size_t)rowBase * Dm;
    const __nv_bfloat16* gBh = Bgh + (size_t)colBase * Dm;
    const __nv_bfloat16* gBl = Bgl + (size_t)colBase * Dm;

    float acc[4][4][4];
    #pragma unroll
    for (int t = 0; t < 4; t++)
        #pragma unroll
        for (int j = 0; j < 4; j++)
            #pragma unroll
            for (int e = 0; e < 4; e++) acc[t][j][e] = 0.f;

    const int r0 = tid >> 2, c0 = tid & 3;
    const int r1 = (tid + 256) >> 2, c1 = (tid + 256) & 3;

    auto issue = [&](int kt, int buf) {
        const int kc = kt * 32;
        const uint32_t base = sb + buf * STAGEB;
        {
            uint32_t so = (uint32_t)(r0 * (GP*2) + c0 * 16);
            size_t  go = (size_t)r0 * Dm + kc + c0 * 8;
            cp16(base + 0*MATB + so, gAh + go);
            cp16(base + 1*MATB + so, gAl + go);
            cp16(base + 2*MATB + so, gBh + go);
            cp16(base + 3*MATB + so, gBl + go);
        }
        {
            uint32_t so = (uint32_t)(r1 * (GP*2) + c1 * 16);
            size_t  go = (size_t)r1 * Dm + kc + c1 * 8;
            cp16(base + 0*MATB + so, gAh + go);
            cp16(base + 1*MATB + so, gAl + go);
            cp16(base + 2*MATB + so, gBh + go);
            cp16(base + 3*MATB + so, gBl + go);
        }
        cp_commit();
    };

    const int aRow = wr * 64 + (lane & 15);
    const int aKh  = (lane >> 4) * 8;
    const int bRowL = wc * 32 + (lane & 7);
    const int bKh   = ((lane >> 3) & 1) * 8;

    issue(0, 0);

    for (int kt = 0; kt < 32; kt++) {
        cp_wait0();
        __syncthreads();
        if (kt + 1 < 32) issue(kt + 1, (kt + 1) & 1);

        const uint32_t base = sb + (kt & 1) * STAGEB;
        #pragma unroll
        for (int kk = 0; kk < 2; kk++) {
            uint32_t bh[4][2], bl[4][2];
            #pragma unroll
            for (int j = 0; j < 4; j++) {
                uint32_t ba = base + 2*MATB +
                    (uint32_t)(((bRowL + j * 8) * GP + kk * 16 + bKh) * 2);
                ldsm_x2(bh[j], ba);
                ldsm_x2(bl[j], ba + MATB);
            }
            #pragma unroll
            for (int t = 0; t < 4; t++) {
                uint32_t aa = base +
                    (uint32_t)(((aRow + t * 16) * GP + kk * 16 + aKh) * 2);
                uint32_t ah[4], al[4];
                ldsm_x4(ah, aa);
                ldsm_x4(al, aa + MATB);
                #pragma unroll
                for (int j = 0; j < 4; j++) {
                    mma16816(acc[t][j], ah, bh[j]);
                    mma16816(acc[t][j], ah, bl[j]);
                    mma16816(acc[t][j], al, bh[j]);
                }
            }
        }
        __syncthreads();
    }

    const int er = lane >> 2, ec = (lane & 3) * 2;
    #pragma unroll
    for (int t = 0; t < 4; t++) {
        #pragma unroll
        for (int j = 0; j < 4; j++) {
            int m0 = rowBase + wr * 64 + t * 16 + er;
            int n  = colBase + wc * 32 + j * 8 + ec;
            float2 lo = make_float2(acc[t][j][0], acc[t][j][1]);
            float2 hi = make_float2(acc[t][j][2], acc[t][j][3]);
            if (split) {
                int h = n >> 6, hd = n & 63;
                int b0 = m0 >> 11, s0 = m0 & 2047;
                int b1 = (m0 + 8) >> 11, s1 = (m0 + 8) & 2047;
                *(float2*)&dst[((size_t)((b0 * Hh + h) * Sq + s0)) * HDc + hd] = lo;
                *(float2*)&dst[((size_t)((b1 * Hh + h) * Sq + s1)) * HDc + hd] = hi;
            } else {
                *(float2*)&dst[(size_t)m0 * Dm + n] = lo;
                *(float2*)&dst[(size_t)(m0 + 8) * Dm + n] = hi;
            }
        }
    }
}

// ---------------------------------------------------------------------------
// HMMA flash attention (split-bf16, causal).
// CTA: 64 q-rows, 4 warps (16 rows/warp), K/V tiles of 64 keys.
// Q,K,V stored in smem as hi/lo bf16 tiles, pitch 72.
// ---------------------------------------------------------------------------
#define AP 72
#define ATB (64*AP*2)   // bytes per tile: 9216

__global__ __launch_bounds__(128) void attn_mma(const float* __restrict__ Qg,
                                                const float* __restrict__ Kg,
                                                const float* __restrict__ Vg,
                                                float* __restrict__ Ag)
{
    extern __shared__ char smc[];
    const uint32_t sb = smem_u32(smc);
    const uint32_t sQh = sb, sQl = sb + ATB, sKh = sb + 2*ATB, sKl = sb + 3*ATB;
    const uint32_t sVh = sb + 4*ATB, sVl = sb + 5*ATB;

    const int tid = threadIdx.x, lane = tid & 31, w = tid >> 5;
    const int q0 = blockIdx.x * 64;
    const int h  = blockIdx.y;
    const int b  = blockIdx.z;

    const float* Qb = Qg + (size_t)((b * Hh + h) * Sq) * HDc;
    const float* Kb = Kg + (size_t)((b * Hh + h) * Sq) * HDc;
    const float* Vb = Vg + (size_t)((b * Hh + h) * Sq) * HDc;

    // load + scale + split Q: 64x64, 1024 float4 chunks
    for (int i = tid; i < 1024; i += 128) {
        int r = i >> 4, c = (i & 15) * 4;
        float4 v = *(const float4*)&Qb[(size_t)(q0 + r) * HDc + c];
        v.x *= 0.125f; v.y *= 0.125f; v.z *= 0.125f; v.w *= 0.125f;
        uint32_t h0, h1, l0, l1;
        h0 = pack_split(v.x, v.y, l0);
        h1 = pack_split(v.z, v.w, l1);
        uint32_t off = (uint32_t)(r * AP + c) * 2;
        *(uint2*)(smc + (sQh - sb) + off) = make_uint2(h0, h1);
        *(uint2*)(smc + (sQl - sb) + off) = make_uint2(l0, l1);
    }

    float m0 = -INFINITY, m1 = -INFINITY, l0s = 0.f, l1s = 0.f;
    float o[8][4];
    #pragma unroll
    for (int j = 0; j < 8; j++)
        #pragma unroll
        for (int e = 0; e < 4; e++) o[j][e] = 0.f;

    const int er = lane >> 2, ec = (lane & 3) * 2;
    const int nTiles = q0 / 64 + 1;

    for (int kt = 0; kt < nTiles; kt++) {
        __syncthreads();
        // load + split K,V tiles (64x64 each)
        for (int i = tid; i < 1024; i += 128) {
            int r = i >> 4, c = (i & 15) * 4;
            size_t go = (size_t)(kt * 64 + r) * HDc + c;
            uint32_t off = (uint32_t)(r * AP + c) * 2;
            float4 kv = *(const float4*)&Kb[go];
            uint32_t h0, h1, lo0, lo1;
            h0 = pack_split(kv.x, kv.y, lo0);
            h1 = pack_split(kv.z, kv.w, lo1);
            *(uint2*)(smc + (sKh - sb) + off) = make_uint2(h0, h1);
            *(uint2*)(smc + (sKl - sb) + off) = make_uint2(lo0, lo1);
            float4 vv = *(const float4*)&Vb[go];
            h0 = pack_split(vv.x, vv.y, lo0);
            h1 = pack_split(vv.z, vv.w, lo1);
            *(uint2*)(smc + (sVh - sb) + off) = make_uint2(h0, h1);
            *(uint2*)(smc + (sVl - sb) + off) = make_uint2(lo0, lo1);
        }
        __syncthreads();

        // scores: S = Q K^T (pre-scaled)
        float s[8][4];
        #pragma unroll
        for (int j = 0; j < 8; j++)
            #pragma unroll
            for (int e = 0; e < 4; e++) s[j][e] = 0.f;

        #pragma unroll
        for (int ks = 0; ks < 4; ks++) {
            uint32_t aoff = (uint32_t)(((w * 16 + (lane & 15)) * AP + ks * 16 + (lane >> 4) * 8) * 2);
            uint32_t ah[4], al[4];
            ldsm_x4(ah, sQh + aoff);
            ldsm_x4(al, sQl + aoff);
            #pragma unroll
            for (int j = 0; j < 8; j++) {
                uint32_t boff = (uint32_t)(((j * 8 + (lane & 7)) * AP + ks * 16 + ((lane >> 3) & 1) * 8) * 2);
                uint32_t bh[2], bl[2];
                ldsm_x2(bh, sKh + boff);
                ldsm_x2(bl, sKl + boff);
                mma16816(s[j], ah, bh);
                mma16816(s[j], ah, bl);
                mma16816(s[j], al, bh);
            }
        }

        const int row0 = q0 + w * 16 + er, row1 = row0 + 8;
        if (kt == nTiles - 1) {   // diagonal tile
            #pragma unroll
            for (int j = 0; j < 8; j++) {
                int k = q0 + j * 8 + ec;
                if (k     > row0) s[j][0] = -INFINITY;
                if (k + 1 > row0) s[j][1] = -INFINITY;
                if (k     > row1) s[j][2] = -INFINITY;
                if (k + 1 > row1) s[j][3] = -INFINITY;
            }
        }

        // online softmax
        float rm0 = -INFINITY, rm1 = -INFINITY;
        #pragma unroll
        for (int j = 0; j < 8; j++) {
            rm0 = fmaxf(rm0, fmaxf(s[j][0], s[j][1]));
            rm1 = fmaxf(rm1, fmaxf(s[j][2], s[j][3]));
        }
        rm0 = fmaxf(rm0, __shfl_xor_sync(0xffffffffu, rm0, 1));
        rm0 = fmaxf(rm0, __shfl_xor_sync(0xffffffffu, rm0, 2));
        rm1 = fmaxf(rm1, __shfl_xor_sync(0xffffffffu, rm1, 1));
        rm1 = fmaxf(rm1, __shfl_xor_sync(0xffffffffu, rm1, 2));
        float mn0 = fmaxf(m0, rm0), mn1 = fmaxf(m1, rm1);
        float c0 = __expf(m0 - mn0), c1 = __expf(m1 - mn1);
        m0 = mn0; m1 = mn1;

        float la0 = 0.f, la1 = 0.f;
        #pragma unroll
        for (int j = 0; j < 8; j++) {
            s[j][0] = __expf(s[j][0] - m0);
            s[j][1] = __expf(s[j][1] - m0);
            s[j][2] = __expf(s[j][2] - m1);
            s[j][3] = __expf(s[j][3] - m1);
            la0 += s[j][0] + s[j][1];
            la1 += s[j][2] + s[j][3];
            o[j][0] *= c0; o[j][1] *= c0;
            o[j][2] *= c1; o[j][3] *= c1;
        }
        l0s = l0s * c0 + la0;
        l1s = l1s * c1 + la1;

        // O += P @ V  (split P, split V)
        #pragma unroll
        for (int aj = 0; aj < 4; aj++) {
            uint32_t ph[4], pl[4];
            ph[0] = pack_split(s[2*aj][0],   s[2*aj][1],   pl[0]);
            ph[1] = pack_split(s[2*aj][2],   s[2*aj][3],   pl[1]);
            ph[2] = pack_split(s[2*aj+1][0], s[2*aj+1][1], pl[2]);
            ph[3] = pack_split(s[2*aj+1][2], s[2*aj+1][3], pl[3]);
            #pragma unroll
            for (int j = 0; j < 8; j++) {
                uint32_t voff = (uint32_t)(((aj * 16 + (lane & 7) + ((lane >> 3) & 1) * 8) * AP + j * 8) * 2);
                uint32_t vh[2], vl[2];
                ldsm_x2t(vh, sVh + voff);
                ldsm_x2t(vl, sVl + voff);
                mma16816(o[j], ph, vh);
                mma16816(o[j], ph, vl);
                mma16816(o[j], pl, vh);
            }
        }
    }

    l0s += __shfl_xor_sync(0xffffffffu, l0s, 1);
    l0s += __shfl_xor_sync(0xffffffffu, l0s, 2);
    l1s += __shfl_xor_sync(0xffffffffu, l1s, 1);
    l1s += __shfl_xor_sync(0xffffffffu, l1s, 2);
    float i0 = 1.f / l0s, i1 = 1.f / l1s;

    const int row0 = q0 + w * 16 + er;
    #pragma unroll
    for (int j = 0; j < 8; j++) {
        int dim = j * 8 + ec;
        *(float2*)&Ag[(size_t)(b * Sq + row0) * Dm + h * HDc + dim] =
            make_float2(o[j][0] * i0, o[j][1] * i0);
        *(float2*)&Ag[(size_t)(b * Sq + row0 + 8) * Dm + h * HDc + dim] =
            make_float2(o[j][2] * i1, o[j][3] * i1);
    }
}

// ---------------------------------------------------------------------------
extern "C" void kernel_launch(void* const* d_in, const int* in_sizes, int n_in,
                              void* d_out, int out_size)
{
    (void)in_sizes; (void)n_in; (void)out_size;
    const float* x  = (const float*)d_in[0];
    const float* WQ = (const float*)d_in[1];
    const float* WK = (const float*)d_in[2];
    const float* WV = (const float*)d_in[3];
    const float* WO = (const float*)d_in[4];
    float* out = (float*)d_out;

    float *qp, *kp, *vp, *ap;
    __nv_bfloat16 *xh, *xl, *wh, *wl, *ah, *al;
    cudaGetSymbolAddress((void**)&qp, g_Q);
    cudaGetSymbolAddress((void**)&kp, g_K);
    cudaGetSymbolAddress((void**)&vp, g_V);
    cudaGetSymbolAddress((void**)&ap, g_A);
    cudaGetSymbolAddress((void**)&xh, g_Xh);
    cudaGetSymbolAddress((void**)&xl, g_Xl);
    cudaGetSymbolAddress((void**)&wh, g_Wh);
    cudaGetSymbolAddress((void**)&wl, g_Wl);
    cudaGetSymbolAddress((void**)&ah, g_AH);
    cudaGetSymbolAddress((void**)&al, g_AL);

    static int attrs_set = 0;
    int gsmem = 2 * STAGEB;       // 81920
    int asmem = 6 * ATB;          // 55296
    if (!attrs_set) {
        cudaFuncSetAttribute(gemm_mma, cudaFuncAttributeMaxDynamicSharedMemorySize, gsmem);
        cudaFuncSetAttribute(attn_mma, cudaFuncAttributeMaxDynamicSharedMemorySize, asmem);
        attrs_set = 1;
    }

    convx_k<<<Mtot * Dm / 4 / 256, 256>>>(x, xh, xl);
    const float* Ws[4] = {WQ, WK, WV, WO};
    for (int i = 0; i < 4; i++)
        convw_k<<<dim3(32, 32), dim3(32, 8)>>>(Ws[i], wh + (size_t)i * Dm * Dm,
                                               wl + (size_t)i * Dm * Dm);

    dim3 gg(Dm / 128, Mtot / 128);
    gemm_mma<<<gg, 256, gsmem>>>(xh, xl, wh + 0 * (size_t)Dm * Dm, wl + 0 * (size_t)Dm * Dm, qp, 1);
    gemm_mma<<<gg, 256, gsmem>>>(xh, xl, wh + 1 * (size_t)Dm * Dm, wl + 1 * (size_t)Dm * Dm, kp, 1);
    gemm_mma<<<gg, 256, gsmem>>>(xh, xl, wh + 2 * (size_t)Dm * Dm, wl + 2 * (size_t)Dm * Dm, vp, 1);

    attn_mma<<<dim3(Sq / 64, Hh, Bq), 128, asmem>>>(qp, kp, vp, ap);

    convx_k<<<Mtot * Dm / 4 / 256, 256>>>(ap, ah, al);
    gemm_mma<<<gg, 256, gsmem>>>(ah, al, wh + 3 * (size_t)Dm * Dm, wl + 3 * (size_t)Dm * Dm, out, 0);
}